// round 8
// baseline (speedup 1.0000x reference)
#include <cuda_runtime.h>
#include <cuda_bf16.h>
#include <math.h>
#include <stdint.h>

#define TSTEPS 5
#define BATCH  128
#define IN0    512
#define HID    1024
#define G4     4096
#define OUTD   32
#define KSPLIT 4

#define BM 128
#define BN 128
#define BK 32
#define NTH 256
#define RS 40            // smem row stride in bf16 (32 data + 8 pad)

// Scratch (device globals; no allocations allowed)
__device__ float g_xg0[TSTEPS * BATCH * G4];
__device__ float g_xg1[TSTEPS * BATCH * G4];
__device__ float g_h1 [TSTEPS * BATCH * HID];
__device__ float g_h2 [TSTEPS * BATCH * HID];
__device__ float g_c  [BATCH * HID];
__device__ __nv_bfloat16 g_hhi[2][BATCH * HID];
__device__ __nv_bfloat16 g_hlo[2][BATCH * HID];
__device__ float g_prt[KSPLIT * BATCH * G4];    // split-K partials, 8 MB
__device__ int   g_arr[8];                      // grid-barrier arrive (per step slot)
__device__ int   g_dep[8];                      // grid-barrier depart

__device__ __forceinline__ uint32_t smem_u32(const void* p) {
    uint32_t a;
    asm("{ .reg .u64 t; cvta.to.shared.u64 t, %1; cvt.u32.u64 %0, t; }"
        : "=r"(a) : "l"(p));
    return a;
}

#define LDSM_X4(R, addr)                                                     \
    asm volatile("ldmatrix.sync.aligned.m8n8.x4.shared.b16 "                 \
                 "{%0,%1,%2,%3}, [%4];"                                      \
                 : "=r"((R)[0]), "=r"((R)[1]), "=r"((R)[2]), "=r"((R)[3])    \
                 : "r"(addr))
#define LDSM_X2(R, addr)                                                     \
    asm volatile("ldmatrix.sync.aligned.m8n8.x2.shared.b16 {%0,%1}, [%2];"   \
                 : "=r"((R)[0]), "=r"((R)[1]) : "r"(addr))
#define MMA_BF16(D, Ar, Br)                                                  \
    asm volatile("mma.sync.aligned.m16n8k16.row.col.f32.bf16.bf16.f32 "      \
                 "{%0,%1,%2,%3}, {%4,%5,%6,%7}, {%8,%9}, {%0,%1,%2,%3};"     \
                 : "+f"((D)[0]), "+f"((D)[1]), "+f"((D)[2]), "+f"((D)[3])    \
                 : "r"((Ar)[0]), "r"((Ar)[1]), "r"((Ar)[2]), "r"((Ar)[3]),   \
                   "r"((Br)[0]), "r"((Br)[1]))

__device__ __forceinline__ void split_bf16(float f, uint16_t& h, uint16_t& l) {
    __nv_bfloat16 hb = __float2bfloat16(f);
    __nv_bfloat16 lb = __float2bfloat16(f - __bfloat162float(hb));
    h = __bfloat16_as_ushort(hb);
    l = __bfloat16_as_ushort(lb);
}
__device__ __forceinline__ float sigf(float x) { return 1.f / (1.f + expf(-x)); }
// Interleaved gate layout: gathered col q <-> natural W row (q&3)*HID + (q>>2)
__device__ __forceinline__ int icol(int q) { return (q & 3) * HID + (q >> 2); }

// ---------------------------------------------------------------------------
// Bulk tensor-core GEMM (XG precompute), interleaved output columns:
// C[r][q] = A[r,:] . W[icol(q),:] + b1[icol(q)] + b2[icol(q)]
// 1 sync per chunk. (proven in R7)
// ---------------------------------------------------------------------------
__global__ __launch_bounds__(NTH) void hmma_gemm(
    const float* __restrict__ A, const float* __restrict__ W,
    int strideA, int strideW, int ksize,
    const float* __restrict__ b1, const float* __restrict__ b2,
    float* __restrict__ C, int ldc)
{
    __shared__ uint16_t sA[2][2][BM * RS];   // [buf][hi/lo]
    __shared__ uint16_t sW[2][2][BN * RS];

    const int tid  = threadIdx.x;
    const int lane = tid & 31;
    const int warp = tid >> 5;
    const int wm   = warp >> 2;
    const int wn   = warp & 3;
    const int row0 = blockIdx.y * BM;
    const int col0 = blockIdx.x * BN;
    const int nch  = ksize / BK;

    const bool isA = (tid < 128);
    const int  t2  = tid & 127;

    float acc[4][4][4];
#pragma unroll
    for (int i = 0; i < 4; i++)
#pragma unroll
        for (int j = 0; j < 4; j++)
#pragma unroll
            for (int v = 0; v < 4; v++) acc[i][j][v] = 0.f;

    float4 pf[8];
#pragma unroll
    for (int i = 0; i < 8; i++) {
        int idx = t2 + 128 * i;
        int r = idx >> 3, c4 = idx & 7;
        const float* src = isA ? (A + (size_t)(row0 + r) * strideA)
                               : (W + (size_t)icol(col0 + r) * strideW);
        pf[i] = *(const float4*)(src + c4 * 4);
    }
    {
        uint16_t* d0 = isA ? sA[0][0] : sW[0][0];
        uint16_t* d1 = isA ? sA[0][1] : sW[0][1];
#pragma unroll
        for (int i = 0; i < 8; i++) {
            int idx = t2 + 128 * i;
            int r = idx >> 3, c4 = idx & 7;
            float f[4] = {pf[i].x, pf[i].y, pf[i].z, pf[i].w};
            uint16_t h[4], l[4];
#pragma unroll
            for (int j = 0; j < 4; j++) split_bf16(f[j], h[j], l[j]);
            int o = r * RS + c4 * 4;
            *(uint2*)(d0 + o) = *(uint2*)h;
            *(uint2*)(d1 + o) = *(uint2*)l;
        }
    }
    __syncthreads();

    const int rl  = lane & 7;
    const int s8  = (lane >> 3) & 1;
    const int s16 = (lane >> 4) & 1;

    for (int c = 0; c < nch; c++) {
        const int buf = c & 1;
        if (c + 1 < nch) {
            const int kk = (c + 1) * BK;
#pragma unroll
            for (int i = 0; i < 8; i++) {
                int idx = t2 + 128 * i;
                int r = idx >> 3, c4 = idx & 7;
                const float* src = isA ? (A + (size_t)(row0 + r) * strideA)
                                       : (W + (size_t)icol(col0 + r) * strideW);
                pf[i] = *(const float4*)(src + kk + c4 * 4);
            }
        }

        const uint32_t aH = smem_u32(sA[buf][0]);
        const uint32_t aL = smem_u32(sA[buf][1]);
        const uint32_t wH = smem_u32(sW[buf][0]);
        const uint32_t wL = smem_u32(sW[buf][1]);
#pragma unroll
        for (int ks = 0; ks < 2; ks++) {
            const int k0b = (ks * 16 + s8 * 8) * 2;
            const int k0a = (ks * 16 + s16 * 8) * 2;
            uint32_t bh[4][2], bl[4][2];
#pragma unroll
            for (int nt = 0; nt < 4; nt++) {
                uint32_t ro = (uint32_t)(wn * 32 + nt * 8 + rl) * (RS * 2) + k0b;
                LDSM_X2(bh[nt], wH + ro);
                LDSM_X2(bl[nt], wL + ro);
            }
#pragma unroll
            for (int mt = 0; mt < 4; mt++) {
                uint32_t ro = (uint32_t)(wm * 64 + mt * 16 + rl + s8 * 8) * (RS * 2) + k0a;
                uint32_t ah[4], al[4];
                LDSM_X4(ah, aH + ro);
                LDSM_X4(al, aL + ro);
#pragma unroll
                for (int nt = 0; nt < 4; nt++) {
                    MMA_BF16(acc[mt][nt], ah, bh[nt]);
                    MMA_BF16(acc[mt][nt], ah, bl[nt]);
                    MMA_BF16(acc[mt][nt], al, bh[nt]);
                }
            }
        }

        if (c + 1 < nch) {
            uint16_t* d0 = isA ? sA[buf ^ 1][0] : sW[buf ^ 1][0];
            uint16_t* d1 = isA ? sA[buf ^ 1][1] : sW[buf ^ 1][1];
#pragma unroll
            for (int i = 0; i < 8; i++) {
                int idx = t2 + 128 * i;
                int r = idx >> 3, c4 = idx & 7;
                float f[4] = {pf[i].x, pf[i].y, pf[i].z, pf[i].w};
                uint16_t h[4], l[4];
#pragma unroll
                for (int j = 0; j < 4; j++) split_bf16(f[j], h[j], l[j]);
                int o = r * RS + c4 * 4;
                *(uint2*)(d0 + o) = *(uint2*)h;
                *(uint2*)(d1 + o) = *(uint2*)l;
            }
        }
        __syncthreads();
    }

#pragma unroll
    for (int mt = 0; mt < 4; mt++) {
        int row = row0 + wm * 64 + mt * 16 + (lane >> 2);
#pragma unroll
        for (int nt = 0; nt < 4; nt++) {
            int col = col0 + wn * 32 + nt * 8 + (lane & 3) * 2;
            float bb0 = b1[icol(col)] + b2[icol(col)];
            float bb1 = b1[icol(col + 1)] + b2[icol(col + 1)];
            float2 v0 = make_float2(acc[mt][nt][0] + bb0, acc[mt][nt][1] + bb1);
            float2 v1 = make_float2(acc[mt][nt][2] + bb0, acc[mt][nt][3] + bb1);
            *(float2*)(C + (size_t)row * ldc + col) = v0;
            *(float2*)(C + (size_t)(row + 8) * ldc + col) = v1;
        }
    }
}

// ---------------------------------------------------------------------------
// Fused step: 128x128-tile split-K GEMM (grid 32x4 = 128 CTAs, 256 thr) +
// in-kernel grid barrier + parallel gates reduction (all 128 CTAs).
// A pre-split bf16 hi/lo; W gathered fp32, split inline.
// ---------------------------------------------------------------------------
__global__ __launch_bounds__(NTH) void step_fused(
    const float* __restrict__ Whh,
    const float* __restrict__ xgt,               // [BATCH][G4] slice for t
    const __nv_bfloat16* __restrict__ hp_hi,
    const __nv_bfloat16* __restrict__ hp_lo,
    __nv_bfloat16* __restrict__ ho_hi,
    __nv_bfloat16* __restrict__ ho_lo,
    float* __restrict__ hseq, int slot)
{
    __shared__ uint16_t sA[2][2][BM * RS];
    __shared__ uint16_t sW[2][2][BN * RS];

    const int tid  = threadIdx.x;
    const int lane = tid & 31;
    const int warp = tid >> 5;
    const int wm   = warp >> 2;
    const int wn   = warp & 3;
    const int bx   = blockIdx.x;                 // n-tile: gathered cols bx*128..
    const int ksl  = blockIdx.y;
    const int kbeg = ksl * (HID / KSPLIT);       // 256

    const bool isA = (tid < 128);
    const int  t2  = tid & 127;
    const __nv_bfloat16* ah = hp_hi + (size_t)t2 * HID + kbeg;
    const __nv_bfloat16* al = hp_lo + (size_t)t2 * HID + kbeg;
    const float* ws = Whh + (size_t)icol(bx * BN + t2) * HID + kbeg;

    float acc[4][4][4];
#pragma unroll
    for (int i = 0; i < 4; i++)
#pragma unroll
        for (int j = 0; j < 4; j++)
#pragma unroll
            for (int v = 0; v < 4; v++) acc[i][j][v] = 0.f;

    uint4 pA[8];           // A: 4 hi + 4 lo ; W: reinterpret as 8 float4
#pragma unroll
    for (int s = 0; s < 4; s++) {
        if (isA) {
            pA[s]     = *(const uint4*)(ah + s * 8);
            pA[4 + s] = *(const uint4*)(al + s * 8);
        } else {
            ((float4*)pA)[s]     = *(const float4*)(ws + s * 4);
            ((float4*)pA)[4 + s] = *(const float4*)(ws + 16 + s * 4);
        }
    }
    // STS chunk 0
    if (isA) {
#pragma unroll
        for (int s = 0; s < 4; s++) {
            *(uint4*)(sA[0][0] + t2 * RS + s * 8) = pA[s];
            *(uint4*)(sA[0][1] + t2 * RS + s * 8) = pA[4 + s];
        }
    } else {
        const float* f = (const float*)pA;
        uint16_t h[32], l[32];
#pragma unroll
        for (int j = 0; j < 32; j++) split_bf16(f[j], h[j], l[j]);
#pragma unroll
        for (int s = 0; s < 4; s++) {
            *(uint4*)(sW[0][0] + t2 * RS + s * 8) = ((uint4*)h)[s];
            *(uint4*)(sW[0][1] + t2 * RS + s * 8) = ((uint4*)l)[s];
        }
    }
    __syncthreads();

    const int rl  = lane & 7;
    const int s8  = (lane >> 3) & 1;
    const int s16 = (lane >> 4) & 1;
    const int nch = (HID / KSPLIT) / BK;         // 8

    for (int c = 0; c < nch; c++) {
        const int buf = c & 1;
        if (c + 1 < nch) {
            const int kk = (c + 1) * BK;
#pragma unroll
            for (int s = 0; s < 4; s++) {
                if (isA) {
                    pA[s]     = *(const uint4*)(ah + kk + s * 8);
                    pA[4 + s] = *(const uint4*)(al + kk + s * 8);
                } else {
                    ((float4*)pA)[s]     = *(const float4*)(ws + kk + s * 4);
                    ((float4*)pA)[4 + s] = *(const float4*)(ws + kk + 16 + s * 4);
                }
            }
        }

        const uint32_t aH = smem_u32(sA[buf][0]);
        const uint32_t aL = smem_u32(sA[buf][1]);
        const uint32_t wH = smem_u32(sW[buf][0]);
        const uint32_t wL = smem_u32(sW[buf][1]);
#pragma unroll
        for (int ks = 0; ks < 2; ks++) {
            const int k0b = (ks * 16 + s8 * 8) * 2;
            const int k0a = (ks * 16 + s16 * 8) * 2;
            uint32_t bh[4][2], bl[4][2];
#pragma unroll
            for (int nt = 0; nt < 4; nt++) {
                uint32_t ro = (uint32_t)(wn * 32 + nt * 8 + rl) * (RS * 2) + k0b;
                LDSM_X2(bh[nt], wH + ro);
                LDSM_X2(bl[nt], wL + ro);
            }
#pragma unroll
            for (int mt = 0; mt < 4; mt++) {
                uint32_t ro = (uint32_t)(wm * 64 + mt * 16 + rl + s8 * 8) * (RS * 2) + k0a;
                uint32_t ahf[4], alf[4];
                LDSM_X4(ahf, aH + ro);
                LDSM_X4(alf, aL + ro);
#pragma unroll
                for (int nt = 0; nt < 4; nt++) {
                    MMA_BF16(acc[mt][nt], ahf, bh[nt]);
                    MMA_BF16(acc[mt][nt], ahf, bl[nt]);
                    MMA_BF16(acc[mt][nt], alf, bh[nt]);
                }
            }
        }

        if (c + 1 < nch) {
            if (isA) {
#pragma unroll
                for (int s = 0; s < 4; s++) {
                    *(uint4*)(sA[buf ^ 1][0] + t2 * RS + s * 8) = pA[s];
                    *(uint4*)(sA[buf ^ 1][1] + t2 * RS + s * 8) = pA[4 + s];
                }
            } else {
                const float* f = (const float*)pA;
                uint16_t h[32], l[32];
#pragma unroll
                for (int j = 0; j < 32; j++) split_bf16(f[j], h[j], l[j]);
#pragma unroll
                for (int s = 0; s < 4; s++) {
                    *(uint4*)(sW[buf ^ 1][0] + t2 * RS + s * 8) = ((uint4*)h)[s];
                    *(uint4*)(sW[buf ^ 1][1] + t2 * RS + s * 8) = ((uint4*)l)[s];
                }
            }
        }
        __syncthreads();
    }

    // ---- store partial tile ----
    float* myp = g_prt + (size_t)ksl * BATCH * G4;
#pragma unroll
    for (int mt = 0; mt < 4; mt++) {
        int row = wm * 64 + mt * 16 + (lane >> 2);
#pragma unroll
        for (int nt = 0; nt < 4; nt++) {
            int col = bx * BN + wn * 32 + nt * 8 + (lane & 3) * 2;
            *(float2*)(myp + (size_t)row * G4 + col) =
                make_float2(acc[mt][nt][0], acc[mt][nt][1]);
            *(float2*)(myp + (size_t)(row + 8) * G4 + col) =
                make_float2(acc[mt][nt][2], acc[mt][nt][3]);
        }
    }

    // ---- grid barrier (128 CTAs, all resident: 128 <= 148 SMs) ----
    __threadfence();
    __syncthreads();
    if (tid == 0) {
        atomicAdd(&g_arr[slot], 1);
        while (atomicAdd(&g_arr[slot], 0) < 128) __nanosleep(32);
    }
    __syncthreads();
    __threadfence();

    // ---- phase 2: parallel gates reduction over all 128 CTAs ----
    const int cta = blockIdx.y * 32 + blockIdx.x;
#pragma unroll
    for (int i = 0; i < 4; i++) {
        int p = cta * 1024 + i * 256 + tid;       // 0..131071 (b, unit)
        int b = p >> 10;
        int u = p & 1023;
        size_t qb = (size_t)b * G4 + u * 4;
        float4 v = *(const float4*)(xgt + qb);
#pragma unroll
        for (int s = 0; s < KSPLIT; s++) {
            float4 pp = __ldcg((const float4*)(g_prt + (size_t)s * BATCH * G4 + qb));
            v.x += pp.x; v.y += pp.y; v.z += pp.z; v.w += pp.w;
        }
        int idx = b * HID + u;
        float cp = g_c[idx];
        float cn = sigf(v.y) * cp + sigf(v.x) * tanhf(v.z);
        float hn = sigf(v.w) * tanhf(cn);
        g_c[idx]  = cn;
        hseq[idx] = hn;
        uint16_t hh, hl;
        split_bf16(hn, hh, hl);
        ho_hi[idx] = __ushort_as_bfloat16(hh);
        ho_lo[idx] = __ushort_as_bfloat16(hl);
    }

    // ---- depart + self-reset (safe for graph replay) ----
    __syncthreads();
    if (tid == 0) {
        int d = atomicAdd(&g_dep[slot], 1);
        if (d == 127) {
            atomicExch(&g_arr[slot], 0);
            __threadfence();
            atomicExch(&g_dep[slot], 0);
        }
    }
}

// ---------------------------------------------------------------------------
// gates0: t=0 (no recurrent term), interleaved xg.
// ---------------------------------------------------------------------------
__global__ __launch_bounds__(256) void gates0(
    const float* __restrict__ xg, float* __restrict__ hseq,
    __nv_bfloat16* __restrict__ hhi, __nv_bfloat16* __restrict__ hlo)
{
    int q  = blockIdx.x * 256 + threadIdx.x;
    int b  = q >> 9;
    int j2 = (q & 511) * 2;
    size_t cb = (size_t)b * G4 + j2 * 4;

    float4 v0 = *(const float4*)(xg + cb);
    float4 v1 = *(const float4*)(xg + cb + 4);

    float cn0 = sigf(v0.x) * tanhf(v0.z);
    float hn0 = sigf(v0.w) * tanhf(cn0);
    float cn1 = sigf(v1.x) * tanhf(v1.z);
    float hn1 = sigf(v1.w) * tanhf(cn1);

    int idx = b * HID + j2;
    *(float2*)(g_c + idx)  = make_float2(cn0, cn1);
    *(float2*)(hseq + idx) = make_float2(hn0, hn1);
    uint16_t h0, l0, h1, l1;
    split_bf16(hn0, h0, l0);
    split_bf16(hn1, h1, l1);
    *(uint32_t*)(hhi + idx) = (uint32_t)h0 | ((uint32_t)h1 << 16);
    *(uint32_t*)(hlo + idx) = (uint32_t)l0 | ((uint32_t)l1 << 16);
}

// ---------------------------------------------------------------------------
// Head: out[b,o] = dot(h2[4][b,:], Wout[o,:]) + bout[o]
// ---------------------------------------------------------------------------
__global__ __launch_bounds__(256) void head_kernel(
    const float* __restrict__ hfin,
    const float* __restrict__ Wout, const float* __restrict__ bout,
    float* __restrict__ out)
{
    __shared__ float hs[HID];
    __shared__ float red[8][32];
    int b = blockIdx.x;
    for (int i = threadIdx.x; i < HID; i += 256) hs[i] = hfin[(size_t)b * HID + i];
    __syncthreads();

    int o     = threadIdx.x % 32;
    int chunk = threadIdx.x / 32;
    float s = 0.f;
    const float* wrow = Wout + (size_t)o * HID;
#pragma unroll 4
    for (int k = chunk * 128; k < chunk * 128 + 128; k++)
        s = fmaf(hs[k], wrow[k], s);
    red[chunk][o] = s;
    __syncthreads();

    if (threadIdx.x < 32) {
        float t = 0.f;
#pragma unroll
        for (int ch = 0; ch < 8; ch++) t += red[ch][threadIdx.x];
        out[(size_t)b * OUTD + threadIdx.x] = t + bout[threadIdx.x];
    }
}

// ---------------------------------------------------------------------------
// Host launcher (12 launches)
// ---------------------------------------------------------------------------
extern "C" void kernel_launch(void* const* d_in, const int* in_sizes, int n_in,
                              void* d_out, int out_size)
{
    const float* input = (const float*)d_in[0];
    const float* w_ih0 = (const float*)d_in[1];
    const float* w_hh0 = (const float*)d_in[2];
    const float* b_ih0 = (const float*)d_in[3];
    const float* b_hh0 = (const float*)d_in[4];
    const float* w_ih1 = (const float*)d_in[5];
    const float* w_hh1 = (const float*)d_in[6];
    const float* b_ih1 = (const float*)d_in[7];
    const float* b_hh1 = (const float*)d_in[8];
    const float* w_out = (const float*)d_in[9];
    const float* b_out = (const float*)d_in[10];
    float* out = (float*)d_out;

    float *xg0, *xg1, *h1, *h2;
    __nv_bfloat16 *hhi, *hlo;
    cudaGetSymbolAddress((void**)&xg0, g_xg0);
    cudaGetSymbolAddress((void**)&xg1, g_xg1);
    cudaGetSymbolAddress((void**)&h1,  g_h1);
    cudaGetSymbolAddress((void**)&h2,  g_h2);
    cudaGetSymbolAddress((void**)&hhi, g_hhi);
    cudaGetSymbolAddress((void**)&hlo, g_hlo);

    const size_t BH = (size_t)BATCH * HID;
    const size_t BG = (size_t)BATCH * G4;

    // 1) XG0 = input[0:640] @ w_ih0^T (interleaved cols) + biases
    {
        dim3 grid(G4 / BN, TSTEPS * BATCH / BM);
        hmma_gemm<<<grid, NTH>>>(input, w_ih0, IN0, IN0, IN0,
                                 b_ih0, b_hh0, xg0, G4);
    }
    // 2) Layer-0 recurrence (GEMM + barrier + gates, one launch per step)
    gates0<<<256, 256>>>(xg0, h1, hhi, hlo);
    for (int t = 1; t < TSTEPS; t++) {
        step_fused<<<dim3(32, KSPLIT), NTH>>>(
            w_hh0, xg0 + (size_t)t * BG,
            hhi + ((t - 1) & 1) * BH, hlo + ((t - 1) & 1) * BH,
            hhi + (t & 1) * BH,       hlo + (t & 1) * BH,
            h1 + (size_t)t * BH, t - 1);
    }
    // 3) XG1 = h1 @ w_ih1^T (interleaved cols) + biases
    {
        dim3 grid(G4 / BN, TSTEPS * BATCH / BM);
        hmma_gemm<<<grid, NTH>>>(h1, w_ih1, HID, HID, HID,
                                 b_ih1, b_hh1, xg1, G4);
    }
    // 4) Layer-1 recurrence
    gates0<<<256, 256>>>(xg1, h2, hhi, hlo);
    for (int t = 1; t < TSTEPS; t++) {
        step_fused<<<dim3(32, KSPLIT), NTH>>>(
            w_hh1, xg1 + (size_t)t * BG,
            hhi + ((t - 1) & 1) * BH, hlo + ((t - 1) & 1) * BH,
            hhi + (t & 1) * BH,       hlo + (t & 1) * BH,
            h2 + (size_t)t * BH, 4 + (t - 1));
    }
    // 5) Linear head on h2[4]
    head_kernel<<<BATCH, 256>>>(h2 + (size_t)4 * BH, w_out, b_out, out);
}